// round 5
// baseline (speedup 1.0000x reference)
#include <cuda_runtime.h>

// FocalTreeMinLoss on GB300 (sm_103a).
// Fixed tree: leaf l -> parent2 = 41 + l%9, grandparent = 50 + l%3.
// Static indexing keeps pred[53] fully in registers.
// Single fused kernel: per-block partial -> deterministic fixed-point u64
// atomic accumulation -> last block finalizes the mean into d_out.

#define NCLS  53
#define NLEAF 41
#define BATCH 4
#define FIXSCALE 16777216.0f   // 2^24

__device__ unsigned long long g_acc;      // zero-init; reset by last block each launch
__device__ unsigned int       g_ticket;   // zero-init; reset by last block each launch

__global__ void __launch_bounds__(256) focal_main(
    const float* __restrict__ cls, const int* __restrict__ label,
    int HW, float* __restrict__ out, int nblocks, double scale)
{
    int hw = blockIdx.x * blockDim.x + threadIdx.x;
    int b  = blockIdx.y;
    float sum = 0.f;

    if (hw < HW) {
        const float* base = cls + (size_t)b * NCLS * HW + hw;
        float pred[NCLS];
#pragma unroll
        for (int c = 0; c < NCLS; c++)
            pred[c] = __ldg(base + (size_t)c * HW);

        int lab = label[(size_t)b * HW + hw];     // 0..40
        int pb  = 41 + lab % 9;
        int pc  = 50 + lab % 3;
        unsigned long long mask =
            (1ull << lab) | (1ull << pb) | (1ull << pc);

        // max over descendants of each second-level node (includes self)
        float m2[9];
#pragma unroll
        for (int k = 0; k < 9; k++) {
            float m = pred[41 + k];
#pragma unroll
            for (int l = k; l < NLEAF; l += 9) m = fmaxf(m, pred[l]);
            m2[k] = m;
        }
        // max over descendants of each top-level node
        float m1[3];
#pragma unroll
        for (int j = 0; j < 3; j++)
            m1[j] = fmaxf(fmaxf(pred[50 + j], m2[j]), fmaxf(m2[j + 3], m2[j + 6]));

#pragma unroll
        for (int c = 0; c < NCLS; c++) {
            bool is_path = (mask >> c) & 1ull;
            float x;
            if (c < NLEAF) {
                float mn = fminf(pred[c], fminf(pred[41 + c % 9], pred[50 + c % 3]));
                x = is_path ? mn : pred[c];
            } else if (c < 50) {
                float mn = fminf(pred[c], pred[50 + (c - 41) % 3]);
                x = is_path ? mn : m2[c - 41];
            } else {
                x = is_path ? pred[c] : m1[c - 50];
            }
            // focal BCE, branch-free, 2 MUFU (EX2, LG2):
            //   u = e^{-|x|}, d = 1+u, L0 = log d, r = 1/d (Newton)
            //   cond = (is_path == (x<0))
            //   bce  = cond ? L0+|x| : L0
            //   w    = cond ? r : u*r          (== |t - sigmoid(x)|)
            float ax = fabsf(x);
            float u  = __expf(-ax);                 // MUFU.EX2
            float d  = 1.f + u;
            float lg = __logf(d);                   // MUFU.LG2
            float r  = fmaf(d, -0.5f, 1.4571f);     // linear minimax seed for 1/d on (1,2]
            r = r * fmaf(d, -r, 2.0f);              // Newton 1
            r = r * fmaf(d, -r, 2.0f);              // Newton 2  (rel err ~5e-5)
            bool  cond = (is_path == (x < 0.f));
            float bce  = cond ? (lg + ax) : lg;
            float w    = (cond ? 1.0f : u) * r;
            sum = fmaf(bce * w, w, sum);
        }
    }

    // block reduction (256 threads = 8 warps)
#pragma unroll
    for (int o = 16; o > 0; o >>= 1)
        sum += __shfl_down_sync(0xffffffffu, sum, o);
    __shared__ float ws[8];
    int lane = threadIdx.x & 31, wid = threadIdx.x >> 5;
    if (lane == 0) ws[wid] = sum;
    __syncthreads();
    if (wid == 0) {
        float s = (lane < 8) ? ws[lane] : 0.f;
#pragma unroll
        for (int o = 4; o > 0; o >>= 1)
            s += __shfl_down_sync(0xffffffffu, s, o);
        if (lane == 0) {
            // deterministic fixed-point accumulation (terms are non-negative)
            unsigned long long v =
                (unsigned long long)__float2ll_rn(s * FIXSCALE);
            atomicAdd(&g_acc, v);
            __threadfence();
            unsigned int t = atomicInc(&g_ticket, 0xffffffffu);
            if (t == (unsigned int)(nblocks - 1)) {
                // last block: read + reset accumulator atomically, finalize
                unsigned long long a = atomicExch(&g_acc, 0ull);
                g_ticket = 0u;
                out[0] = (float)((double)a * scale);
            }
        }
    }
}

extern "C" void kernel_launch(void* const* d_in, const int* in_sizes, int n_in,
                              void* d_out, int out_size)
{
    const float* cls   = (const float*)d_in[0];
    const int*   label = (const int*)d_in[1];
    int N  = in_sizes[1];        // B*H*W
    int HW = N / BATCH;          // H*W
    int C  = in_sizes[0] / N;    // 53

    dim3 grid((HW + 255) / 256, BATCH);
    int nblocks = grid.x * grid.y;
    double scale = 1.0 / ((double)N * (double)C * (double)FIXSCALE);
    focal_main<<<grid, 256>>>(cls, label, HW, (float*)d_out, nblocks, scale);
}